// round 17
// baseline (speedup 1.0000x reference)
#include <cuda_runtime.h>
#include <cuda_fp16.h>
#include <cstdint>
#include <math.h>

#define B_ 4
#define H_ 16
#define S_ 2048
#define D_ 1024
#define BH 64
#define dh 64
#define NEGV (-1000000.0f)

// ============================ device scratch ============================
__device__ __half g_Yhi[(size_t)BH * S_ * dh];
__device__ __half g_Ylo[(size_t)BH * S_ * dh];
__device__ __half g_XhiT[(size_t)BH * dh * S_];   // [bh][c][s]

// ============================ PTX helpers ============================
__device__ __forceinline__ uint32_t smem_u32(const void* p) {
    uint32_t a;
    asm("{ .reg .u64 t; cvta.to.shared.u64 t, %1; cvt.u32.u64 %0, t; }" : "=r"(a) : "l"(p));
    return a;
}
#define LDSM_X4(r0, r1, r2, r3, addr) \
    asm volatile("ldmatrix.sync.aligned.m8n8.x4.shared.b16 {%0,%1,%2,%3}, [%4];" \
        : "=r"(r0), "=r"(r1), "=r"(r2), "=r"(r3) : "r"(addr))
#define CP_ASYNC16(dst, src) \
    asm volatile("cp.async.cg.shared.global [%0], [%1], 16;" :: "r"(dst), "l"(src))
#define CP_COMMIT() asm volatile("cp.async.commit_group;")
#define CP_WAIT0()  asm volatile("cp.async.wait_group 0;")

__device__ __forceinline__ void mma16816(float d[4], const uint32_t a[4], const uint32_t b[2]) {
    asm volatile(
        "mma.sync.aligned.m16n8k16.row.col.f32.f16.f16.f32 "
        "{%0,%1,%2,%3}, {%4,%5,%6,%7}, {%8,%9}, {%0,%1,%2,%3};"
        : "+f"(d[0]), "+f"(d[1]), "+f"(d[2]), "+f"(d[3])
        : "r"(a[0]), "r"(a[1]), "r"(a[2]), "r"(a[3]), "r"(b[0]), "r"(b[1]));
}
__device__ __forceinline__ uint32_t packh(float a, float b) {
    __half2 h = __floats2half2_rn(a, b);
    return *(uint32_t*)&h;
}

// 16B-granule swizzle for the prep x-tiles: kills the 16-way gather conflict.
#define XSW(byte, row) ((uint32_t)(byte) ^ (((((uint32_t)(row)) >> 3) & 7u) << 4))

// ============================ fused prep (round-14 winner, unchanged) ============================
#define PROWB 144
#define PSXL 18432
#define PSWH 36864
#define PSWL 46080
#define PREP_SMEM 55296

__global__ void __launch_bounds__(256, 1) prep_mma(const float* __restrict__ x,
                                                   const float* __restrict__ W,
                                                   const float* __restrict__ bias) {
    extern __shared__ char smem[];
    uint32_t sb = smem_u32(smem);
    int tid = threadIdx.x;
    int w = tid >> 5, l = tid & 31;
    int bh = blockIdx.x >> 4;
    int s0 = (blockIdx.x & 15) * 128;
    int b = bh >> 4, h = bh & 15;

    #pragma unroll
    for (int t = 0; t < 16; t++) {
        int idx = t * 256 + tid;
        int i = idx >> 6, j = idx & 63;
        float v = W[idx];
        __half hi = __float2half_rn(v);
        *(__half*)(smem + PSWH + j * PROWB + i * 2) = hi;
        *(__half*)(smem + PSWL + j * PROWB + i * 2) = __float2half_rn(v - __half2float(hi));
    }

    #pragma unroll
    for (int t = 0; t < 8; t++) {
        int idx = t * 256 + tid;
        int row = idx >> 4, q = idx & 15;
        float4 v = *(const float4*)(x + (size_t)(b * S_ + s0 + row) * D_ + h * 64 + q * 4);
        __half h0 = __float2half_rn(v.x), h1 = __float2half_rn(v.y);
        __half h2 = __float2half_rn(v.z), h3 = __float2half_rn(v.w);
        uint2 hiw = make_uint2(packh(v.x, v.y), packh(v.z, v.w));
        uint2 low = make_uint2(packh(v.x - __half2float(h0), v.y - __half2float(h1)),
                               packh(v.z - __half2float(h2), v.w - __half2float(h3)));
        uint32_t off = XSW((uint32_t)row * PROWB + (uint32_t)q * 8, row);
        *(uint2*)(smem + off) = hiw;
        *(uint2*)(smem + PSXL + off) = low;
    }
    __syncthreads();

    #pragma unroll
    for (int t = 0; t < 4; t++) {
        int u = t * 256 + tid;
        int c = (u >> 4) & 63;
        int g8 = u & 15;
        uint32_t pk[4];
        #pragma unroll
        for (int p = 0; p < 4; p++) {
            int r0 = g8 * 8 + 2 * p, r1 = r0 + 1;
            uint16_t a0 = *(const uint16_t*)(smem + XSW((uint32_t)r0 * PROWB + c * 2, r0));
            uint16_t a1 = *(const uint16_t*)(smem + XSW((uint32_t)r1 * PROWB + c * 2, r1));
            pk[p] = (uint32_t)a0 | ((uint32_t)a1 << 16);
        }
        __half* dst = g_XhiT + ((size_t)bh * 64 + c) * S_ + s0 + g8 * 8;
        *(uint4*)dst = *(uint4*)pk;
    }

    uint32_t ahi[4][4], alo[4][4];
    #pragma unroll
    for (int j = 0; j < 4; j++) {
        int arow = w * 16 + (l & 15);
        uint32_t off = XSW((uint32_t)arow * PROWB + (uint32_t)(((l >> 4) * 8 + 16 * j) * 2), arow);
        LDSM_X4(ahi[j][0], ahi[j][1], ahi[j][2], ahi[j][3], sb + off);
        LDSM_X4(alo[j][0], alo[j][1], alo[j][2], alo[j][3], sb + PSXL + off);
    }

    int R0 = w * 16 + (l >> 2);
    #pragma unroll
    for (int t2 = 0; t2 < 8; t2++) {
        uint32_t b0 = sb + PSWH + (uint32_t)(t2 * 8 + (l & 7)) * PROWB +
                      (uint32_t)(((l >> 3) * 8) * 2);
        uint32_t bh0, bh1, bh2, bh3, bh4, bh5, bh6, bh7;
        uint32_t bl0, bl1, bl2, bl3, bl4, bl5, bl6, bl7;
        LDSM_X4(bh0, bh1, bh2, bh3, b0);
        LDSM_X4(bh4, bh5, bh6, bh7, b0 + 64u);
        LDSM_X4(bl0, bl1, bl2, bl3, b0 + (PSWL - PSWH));
        LDSM_X4(bl4, bl5, bl6, bl7, b0 + (PSWL - PSWH) + 64u);
        uint32_t bhv[8] = {bh0, bh1, bh2, bh3, bh4, bh5, bh6, bh7};
        uint32_t blv[8] = {bl0, bl1, bl2, bl3, bl4, bl5, bl6, bl7};

        float y[4] = {0.0f, 0.0f, 0.0f, 0.0f};
        #pragma unroll
        for (int j = 0; j < 4; j++) {
            mma16816(y, ahi[j], &bhv[2 * j]);
            mma16816(y, alo[j], &bhv[2 * j]);
            mma16816(y, ahi[j], &blv[2 * j]);
        }

        int c = t2 * 8 + (l & 3) * 2;
        float b0f = bias[c], b1f = bias[c + 1];
        y[0] += b0f; y[1] += b1f; y[2] += b0f; y[3] += b1f;

        __half h0 = __float2half_rn(y[0]), h1 = __float2half_rn(y[1]);
        __half h2 = __float2half_rn(y[2]), h3 = __float2half_rn(y[3]);
        size_t o0 = ((size_t)bh * S_ + s0 + R0) * 64 + c;
        size_t o1 = ((size_t)bh * S_ + s0 + R0 + 8) * 64 + c;
        *(uint32_t*)(g_Yhi + o0) = packh(y[0], y[1]);
        *(uint32_t*)(g_Yhi + o1) = packh(y[2], y[3]);
        *(uint32_t*)(g_Ylo + o0) = packh(y[0] - __half2float(h0), y[1] - __half2float(h1));
        *(uint32_t*)(g_Ylo + o1) = packh(y[2] - __half2float(h2), y[3] - __half2float(h3));
    }
}

// ============================ attention kernel ============================
// Round-16 math (2-term scores, 1-term PV). NEW: __launch_bounds__(256, 2)
// for 2 independent CTAs/SM (cross-CTA tensor/MUFU overlap) + half-split
// loop (bit-identical numerics) to shrink live registers so 128 fits.
#define STG 18432
#define STG_BASE 36864
#define ROWB 144
#define ATTN_SMEM 73728

__device__ __forceinline__ void load_stage(uint32_t base, int bh, int kt, int tid) {
    #pragma unroll
    for (int t = 0; t < 4; t++) {
        int tile = t >> 1;                      // 0: Yhi, 1: XhiT
        int idx  = ((t & 1) << 8) + tid;        // 0..511
        int n = idx >> 3, o = idx & 7;
        uint32_t dst = base + (uint32_t)tile * 9216u + (uint32_t)n * ROWB + (uint32_t)o * 16u;
        const __half* src;
        if (tile == 0) src = g_Yhi  + ((size_t)bh * S_ + kt * 64 + n) * 64 + o * 8;
        else           src = g_XhiT + ((size_t)bh * 64 + n) * S_ + kt * 64 + o * 8;
        CP_ASYNC16(dst, src);
    }
    CP_COMMIT();
}

__global__ void __launch_bounds__(256, 2) attn_mma(const int* __restrict__ mask,
                                                   float* __restrict__ out) {
    extern __shared__ char smem[];
    uint32_t sb = smem_u32(smem);
    int tid = threadIdx.x;
    int w = tid >> 5, l = tid & 31;
    int bh = blockIdx.y, b = bh >> 4;
    int q0 = blockIdx.x * 128;

    // ---- Yq (hi/lo) into [0, 36864) via cp.async ----
    #pragma unroll
    for (int t = 0; t < 8; t++) {
        int sel = t >> 2;
        int ii  = ((t & 3) << 8) + tid;
        int row = ii >> 3, o = ii & 7;
        uint32_t dst = sb + (uint32_t)sel * 18432u + (uint32_t)row * ROWB + (uint32_t)o * 16u;
        const __half* src = (sel ? g_Ylo : g_Yhi) + ((size_t)bh * S_ + q0 + row) * 64 + o * 8;
        CP_ASYNC16(dst, src);
    }
    CP_COMMIT();
    // prefetch ktile 0 into stage1 (no overlap with Yq region)
    load_stage(sb + STG_BASE + STG, bh, 0, tid);
    CP_WAIT0();
    __syncthreads();

    // ---- extract Yq A-fragments ----
    uint32_t ahi[4][4], alo[4][4];
    #pragma unroll
    for (int j = 0; j < 4; j++) {
        uint32_t ad = sb + (uint32_t)(w * 16 + (l & 15)) * ROWB +
                      (uint32_t)(((l >> 4) * 8 + 16 * j) * 2);
        LDSM_X4(ahi[j][0], ahi[j][1], ahi[j][2], ahi[j][3], ad);
        LDSM_X4(alo[j][0], alo[j][1], alo[j][2], alo[j][3], ad + 18432u);
    }

    int R0 = q0 + w * 16 + (l >> 2);
    float negv0 = (1.0f - (float)mask[(size_t)b * S_ + R0]) * NEGV;
    float negv1 = (1.0f - (float)mask[(size_t)b * S_ + R0 + 8]) * NEGV;

    float pv[8][4];
    #pragma unroll
    for (int t = 0; t < 8; t++)
        #pragma unroll
        for (int q = 0; q < 4; q++) pv[t][q] = 0.0f;
    float l0 = 0.0f, l1 = 0.0f;

    for (int kt = 0; kt < 32; kt++) {
        uint32_t cur = sb + STG_BASE + (uint32_t)((kt + 1) & 1) * STG;
        if (kt < 31) load_stage(sb + STG_BASE + (uint32_t)(kt & 1) * STG, bh, kt + 1, tid);

        #pragma unroll
        for (int half = 0; half < 2; half++) {
            uint32_t pA[2][4];   // P for this half's 32 keys

            // ---- scores (2-term) + softmax + pack ----
            #pragma unroll
            for (int tt = 0; tt < 4; tt++) {
                int t = half * 4 + tt;
                uint32_t b0 = cur + (uint32_t)(t * 8 + (l & 7)) * ROWB +
                              (uint32_t)(((l >> 3) * 8) * 2);
                uint32_t bh0, bh1, bh2, bh3, bh4, bh5, bh6, bh7;
                LDSM_X4(bh0, bh1, bh2, bh3, b0);
                LDSM_X4(bh4, bh5, bh6, bh7, b0 + 64u);
                uint32_t bhv[8] = {bh0, bh1, bh2, bh3, bh4, bh5, bh6, bh7};

                float s[4] = {0.0f, 0.0f, 0.0f, 0.0f};
                #pragma unroll
                for (int j = 0; j < 4; j++) {
                    mma16816(s, ahi[j], &bhv[2 * j]);
                    mma16816(s, alo[j], &bhv[2 * j]);
                }

                float lg0 = __fadd_rn(__fmul_rn(s[0], 0.015625f), negv0);
                float lg1 = __fadd_rn(__fmul_rn(s[1], 0.015625f), negv0);
                float lg2 = __fadd_rn(__fmul_rn(s[2], 0.015625f), negv1);
                float lg3 = __fadd_rn(__fmul_rn(s[3], 0.015625f), negv1);
                float p0 = __expf(lg0 - negv0);
                float p1 = __expf(lg1 - negv0);
                float p2 = __expf(lg2 - negv1);
                float p3 = __expf(lg3 - negv1);
                l0 += p0 + p1;
                l1 += p2 + p3;

                pA[tt >> 1][(tt & 1) * 2 + 0] = packh(p0, p1);
                pA[tt >> 1][(tt & 1) * 2 + 1] = packh(p2, p3);
            }

            // ---- PV for this half's 32 keys (byte offset half*64) ----
            #pragma unroll
            for (int t2 = 0; t2 < 8; t2++) {
                uint32_t b0 = cur + 9216u + (uint32_t)(t2 * 8 + (l & 7)) * ROWB +
                              (uint32_t)(((l >> 3) * 8) * 2) + (uint32_t)half * 64u;
                uint32_t bh0, bh1, bh2, bh3;
                LDSM_X4(bh0, bh1, bh2, bh3, b0);
                uint32_t bhv[4] = {bh0, bh1, bh2, bh3};
                mma16816(pv[t2], pA[0], &bhv[0]);
                mma16816(pv[t2], pA[1], &bhv[2]);
            }
        }

        CP_WAIT0();
        __syncthreads();
    }

    // ---- epilogue ----
    l0 += __shfl_xor_sync(0xffffffffu, l0, 1);
    l0 += __shfl_xor_sync(0xffffffffu, l0, 2);
    l1 += __shfl_xor_sync(0xffffffffu, l1, 1);
    l1 += __shfl_xor_sync(0xffffffffu, l1, 2);
    float i0 = 1.0f / l0, i1 = 1.0f / l1;

    #pragma unroll
    for (int t2 = 0; t2 < 8; t2++) {
        int c = t2 * 8 + (l & 3) * 2;
        float2 v0 = make_float2(pv[t2][0] * i0, pv[t2][1] * i0);
        float2 v1 = make_float2(pv[t2][2] * i1, pv[t2][3] * i1);
        *(float2*)(out + ((size_t)bh * S_ + R0) * 64 + c)     = v0;
        *(float2*)(out + ((size_t)bh * S_ + R0 + 8) * 64 + c) = v1;
    }
}

// ============================ launch ============================
extern "C" void kernel_launch(void* const* d_in, const int* in_sizes, int n_in,
                              void* d_out, int out_size) {
    const float* x    = (const float*)d_in[0];
    const int*   mask = (const int*)d_in[1];
    const float* W    = (const float*)d_in[2];
    const float* bias = (const float*)d_in[3];
    float* out = (float*)d_out;

    cudaFuncSetAttribute(prep_mma, cudaFuncAttributeMaxDynamicSharedMemorySize, PREP_SMEM);
    prep_mma<<<BH * 16, 256, PREP_SMEM>>>(x, W, bias);

    cudaFuncSetAttribute(attn_mma, cudaFuncAttributeMaxDynamicSharedMemorySize, ATTN_SMEM);
    dim3 grid(S_ / 128, BH);
    attn_mma<<<grid, 256, ATTN_SMEM>>>(mask, out);
}